// round 5
// baseline (speedup 1.0000x reference)
#include <cuda_runtime.h>

#define N_NODES 100000
#define N_EDGES 1600000
#define IN_DIM 128
#define HID_DIM 128
#define OUT_DIM 64

#define SCAN_TPB 512
#define SCAN_BLOCKS ((N_NODES + SCAN_TPB - 1) / SCAN_TPB)   // 196

// ---------------- device scratch ------------------------------------------------
__device__ int   g_deg[N_NODES];
__device__ int   g_rowptr[N_NODES + 1];
__device__ int   g_blocksum[SCAN_BLOCKS];
__device__ int   g_cursor[N_NODES];
__device__ int   g_csrc[N_EDGES];
__device__ float g_dis[N_NODES];
__device__ float g_h1[(size_t)N_NODES * HID_DIM];    // x @ W1
__device__ float g_agg1[(size_t)N_NODES * HID_DIM];  // relu(A_hat h1 + b1)
__device__ float g_h2[(size_t)N_NODES * OUT_DIM];    // agg1 @ W2

// ---------------- packed fp32x2 FMA (sm_103a) ------------------------------------
__device__ __forceinline__ void ffma2(unsigned long long& c,
                                      unsigned long long a,
                                      unsigned long long b) {
    asm("fma.rn.f32x2 %0, %1, %2, %0;" : "+l"(c) : "l"(a), "l"(b));
}

// ---------------- degree / norm -------------------------------------------------
__global__ void deg_kernel(const int* __restrict__ dst, int* __restrict__ deg) {
    int i = blockIdx.x * blockDim.x + threadIdx.x;
    if (i < N_EDGES) atomicAdd(&deg[dst[i]], 1);
}

__global__ void dis_kernel(const int* __restrict__ deg, float* __restrict__ dis) {
    int i = blockIdx.x * blockDim.x + threadIdx.x;
    if (i < N_NODES) {
        float d = (float)deg[i];
        dis[i] = (d > 0.0f) ? rsqrtf(d) : 0.0f;
    }
}

// ---------------- 3-pass exclusive scan -> rowptr -------------------------------
__global__ void scan_pass1(const int* __restrict__ deg, int* __restrict__ blocksum) {
    __shared__ int warpsum[SCAN_TPB / 32];
    int idx = blockIdx.x * SCAN_TPB + threadIdx.x;
    int v = (idx < N_NODES) ? deg[idx] : 0;
    for (int o = 16; o > 0; o >>= 1) v += __shfl_down_sync(0xffffffff, v, o);
    if ((threadIdx.x & 31) == 0) warpsum[threadIdx.x >> 5] = v;
    __syncthreads();
    if (threadIdx.x < SCAN_TPB / 32) {
        int s = warpsum[threadIdx.x];
        for (int o = 8; o > 0; o >>= 1) s += __shfl_down_sync(0xffff, s, o);
        if (threadIdx.x == 0) blocksum[blockIdx.x] = s;
    }
}

// parallel exclusive scan of the 196 block sums (one 256-thread block)
__global__ void scan_pass2(int* __restrict__ blocksum, int* __restrict__ rowptr) {
    __shared__ int ws[8];
    int lane = threadIdx.x & 31;
    int wid  = threadIdx.x >> 5;
    int v = (threadIdx.x < SCAN_BLOCKS) ? blocksum[threadIdx.x] : 0;
    int sc = v;
    for (int o = 1; o < 32; o <<= 1) {
        int t = __shfl_up_sync(0xffffffff, sc, o);
        if (lane >= o) sc += t;
    }
    if (lane == 31) ws[wid] = sc;
    __syncthreads();
    if (wid == 0 && lane < 8) {
        int s = ws[lane], ss = s;
        for (int o = 1; o < 8; o <<= 1) {
            int t = __shfl_up_sync(0xff, ss, o);
            if (lane >= o) ss += t;
        }
        ws[lane] = ss - s;
    }
    __syncthreads();
    if (threadIdx.x < SCAN_BLOCKS) blocksum[threadIdx.x] = ws[wid] + sc - v;  // exclusive
    if (threadIdx.x == 0) rowptr[N_NODES] = N_EDGES;
}

__global__ void scan_pass3(const int* __restrict__ deg, const int* __restrict__ blocksum,
                           int* __restrict__ rowptr) {
    __shared__ int warpsum[SCAN_TPB / 32];
    int idx = blockIdx.x * SCAN_TPB + threadIdx.x;
    int lane = threadIdx.x & 31;
    int wid  = threadIdx.x >> 5;
    int v = (idx < N_NODES) ? deg[idx] : 0;
    int sc = v;
    for (int o = 1; o < 32; o <<= 1) {
        int t = __shfl_up_sync(0xffffffff, sc, o);
        if (lane >= o) sc += t;
    }
    if (lane == 31) warpsum[wid] = sc;
    __syncthreads();
    if (wid == 0 && lane < SCAN_TPB / 32) {
        int s = warpsum[lane];
        int ss = s;
        for (int o = 1; o < SCAN_TPB / 32; o <<= 1) {
            int t = __shfl_up_sync(0xffff, ss, o);
            if (lane >= o) ss += t;
        }
        warpsum[lane] = ss - s;
    }
    __syncthreads();
    if (idx < N_NODES)
        rowptr[idx] = blocksum[blockIdx.x] + warpsum[wid] + (sc - v);
}

// ---------------- CSR fill -------------------------------------------------------
__global__ void fill_kernel(const int* __restrict__ src, const int* __restrict__ dst,
                            const int* __restrict__ rowptr, int* __restrict__ cursor,
                            int* __restrict__ csrc) {
    int e = blockIdx.x * blockDim.x + threadIdx.x;
    if (e < N_EDGES) {
        int d = dst[e];
        int pos = rowptr[d] + atomicAdd(&cursor[d], 1);
        csrc[pos] = src[e];
    }
}

// ---------------- SGEMM (FFMA2): C[M,BN] = A[M,128] @ B[128,BN] -------------------
// BM=128, BK=16, 256 threads. A tile stored DUPLICATED (each value twice) so the
// broadcast operand of fma.rn.f32x2 loads directly as a 64-bit pair.
template<int BN, int TN>
__global__ void __launch_bounds__(256) gemm128_kernel(const float* __restrict__ A,
                                                      const float* __restrict__ B,
                                                      float* __restrict__ C, int M) {
    constexpr int BM = 128;
    constexpr int BK = 16;
    constexpr int AS_STRIDE = 2 * BM + 4;     // +4 floats pad: stagger banks per k-row
    __shared__ float As2[BK * AS_STRIDE];
    __shared__ float Bs[BK][BN];

    const int tid = threadIdx.x;
    const int m0 = blockIdx.x * BM;
    const int tx = tid & 15;
    const int ty = tid >> 4;
    const int row = ty * 8;
    const int col = tx * TN;

    unsigned long long acc[8][TN / 2];
#pragma unroll
    for (int i = 0; i < 8; i++)
#pragma unroll
        for (int j = 0; j < TN / 2; j++) acc[i][j] = 0ull;

    for (int kt = 0; kt < 128; kt += BK) {
        __syncthreads();
        // ---- A tile: 512 float4 loads (2 per thread), store duplicated+transposed
#pragma unroll
        for (int it = 0; it < 2; it++) {
            int idx = tid + it * 256;        // 0..511
            int r   = idx >> 2;              // 0..127
            int cg  = idx & 3;               // which float4 of the 16 k-cols
            int gm  = m0 + r;
            float4 v = make_float4(0.f, 0.f, 0.f, 0.f);
            if (gm < M) v = *(const float4*)(A + (long long)gm * 128 + kt + cg * 4);
            float* p0 = &As2[(cg * 4 + 0) * AS_STRIDE + 2 * r];
            float* p1 = &As2[(cg * 4 + 1) * AS_STRIDE + 2 * r];
            float* p2 = &As2[(cg * 4 + 2) * AS_STRIDE + 2 * r];
            float* p3 = &As2[(cg * 4 + 3) * AS_STRIDE + 2 * r];
            *(float2*)p0 = make_float2(v.x, v.x);
            *(float2*)p1 = make_float2(v.y, v.y);
            *(float2*)p2 = make_float2(v.z, v.z);
            *(float2*)p3 = make_float2(v.w, v.w);
        }
        // ---- B tile: contiguous copy of rows kt..kt+15
        {
            const float4* bsrc = (const float4*)(B + kt * BN);
            float4* bdst = (float4*)(&Bs[0][0]);
#pragma unroll
            for (int idx = tid; idx < BK * BN / 4; idx += 256) bdst[idx] = bsrc[idx];
        }
        __syncthreads();
        // ---- compute: 8 a-pairs (duplicated) x TN/2 b-pairs of FFMA2
#pragma unroll
        for (int k = 0; k < BK; k++) {
            unsigned long long a2[8];
            const float* abase = &As2[k * AS_STRIDE + 2 * row];
            {
                ulonglong2 t0 = *(const ulonglong2*)(abase + 0);
                ulonglong2 t1 = *(const ulonglong2*)(abase + 4);
                ulonglong2 t2 = *(const ulonglong2*)(abase + 8);
                ulonglong2 t3 = *(const ulonglong2*)(abase + 12);
                a2[0] = t0.x; a2[1] = t0.y; a2[2] = t1.x; a2[3] = t1.y;
                a2[4] = t2.x; a2[5] = t2.y; a2[6] = t3.x; a2[7] = t3.y;
            }
            unsigned long long b2[TN / 2];
#pragma unroll
            for (int j = 0; j < TN / 2; j += 2) {
                // pairs (col+2j, col+2j+1) and (col+2j+2, col+2j+3)
                ulonglong2 t = *(const ulonglong2*)&Bs[k][col + 2 * j];
                b2[j] = t.x; b2[j + 1] = t.y;
            }
#pragma unroll
            for (int i = 0; i < 8; i++)
#pragma unroll
                for (int j = 0; j < TN / 2; j++) ffma2(acc[i][j], a2[i], b2[j]);
        }
    }
    // ---- store (acc pairs reinterpret to floats, layout identical to scalar)
#pragma unroll
    for (int i = 0; i < 8; i++) {
        int gm = m0 + row + i;
        if (gm < M) {
#pragma unroll
            for (int j = 0; j < TN / 2; j += 2)
                *(float4*)(C + (long long)gm * BN + col + 2 * j) = *(const float4*)&acc[i][j];
        }
    }
}

// ---------------- CSR gather: one warp per node ----------------------------------
template<bool RELU>
__global__ void gather128_kernel(const int* __restrict__ rowptr,
                                 const int* __restrict__ csrc,
                                 const float* __restrict__ dis,
                                 const float* __restrict__ h,
                                 const float* __restrict__ bias,
                                 float* __restrict__ out) {
    const int lane = threadIdx.x & 31;
    const int node = blockIdx.x * (blockDim.x >> 5) + (threadIdx.x >> 5);
    if (node >= N_NODES) return;

    const int start = rowptr[node];
    const int end   = rowptr[node + 1];
    float4 acc = make_float4(0.f, 0.f, 0.f, 0.f);

    int j = start;
    for (; j + 2 <= end; j += 2) {
        int s0 = csrc[j], s1 = csrc[j + 1];
        float w0 = dis[s0], w1 = dis[s1];
        float4 v0 = ((const float4*)(h + (long long)s0 * 128))[lane];
        float4 v1 = ((const float4*)(h + (long long)s1 * 128))[lane];
        acc.x += w0 * v0.x + w1 * v1.x;
        acc.y += w0 * v0.y + w1 * v1.y;
        acc.z += w0 * v0.z + w1 * v1.z;
        acc.w += w0 * v0.w + w1 * v1.w;
    }
    if (j < end) {
        int s0 = csrc[j];
        float w0 = dis[s0];
        float4 v0 = ((const float4*)(h + (long long)s0 * 128))[lane];
        acc.x += w0 * v0.x; acc.y += w0 * v0.y; acc.z += w0 * v0.z; acc.w += w0 * v0.w;
    }

    float dn = dis[node];
    float4 bv = ((const float4*)bias)[lane];
    float4 r;
    r.x = dn * acc.x + bv.x;
    r.y = dn * acc.y + bv.y;
    r.z = dn * acc.z + bv.z;
    r.w = dn * acc.w + bv.w;
    if (RELU) {
        r.x = fmaxf(r.x, 0.f); r.y = fmaxf(r.y, 0.f);
        r.z = fmaxf(r.z, 0.f); r.w = fmaxf(r.w, 0.f);
    }
    ((float4*)(out + (long long)node * 128))[lane] = r;
}

__global__ void gather64_kernel(const int* __restrict__ rowptr,
                                const int* __restrict__ csrc,
                                const float* __restrict__ dis,
                                const float* __restrict__ h,
                                const float* __restrict__ bias,
                                float* __restrict__ out) {
    const int lane = threadIdx.x & 31;
    const int node = blockIdx.x * (blockDim.x >> 5) + (threadIdx.x >> 5);
    if (node >= N_NODES) return;

    const int start = rowptr[node];
    const int end   = rowptr[node + 1];
    float2 acc = make_float2(0.f, 0.f);

    int j = start;
    for (; j + 2 <= end; j += 2) {
        int s0 = csrc[j], s1 = csrc[j + 1];
        float w0 = dis[s0], w1 = dis[s1];
        float2 v0 = ((const float2*)(h + (long long)s0 * 64))[lane];
        float2 v1 = ((const float2*)(h + (long long)s1 * 64))[lane];
        acc.x += w0 * v0.x + w1 * v1.x;
        acc.y += w0 * v0.y + w1 * v1.y;
    }
    if (j < end) {
        int s0 = csrc[j];
        float w0 = dis[s0];
        float2 v0 = ((const float2*)(h + (long long)s0 * 64))[lane];
        acc.x += w0 * v0.x; acc.y += w0 * v0.y;
    }

    float dn = dis[node];
    float2 bv = ((const float2*)bias)[lane];
    float2 r;
    r.x = dn * acc.x + bv.x;
    r.y = dn * acc.y + bv.y;
    ((float2*)(out + (long long)node * 64))[lane] = r;
}

// ---------------- launch ----------------------------------------------------------
extern "C" void kernel_launch(void* const* d_in, const int* in_sizes, int n_in,
                              void* d_out, int out_size) {
    const float* x   = (const float*)d_in[0];
    const int*   ei  = (const int*)d_in[1];   // [2, E] int32
    const float* W1  = (const float*)d_in[2];
    const float* b1  = (const float*)d_in[3];
    const float* W2  = (const float*)d_in[4];
    const float* b2  = (const float*)d_in[5];
    float*       out = (float*)d_out;

    const int* src = ei;
    const int* dst = ei + N_EDGES;

    int*   deg;      cudaGetSymbolAddress((void**)&deg,      g_deg);
    int*   rowptr;   cudaGetSymbolAddress((void**)&rowptr,   g_rowptr);
    int*   blocksum; cudaGetSymbolAddress((void**)&blocksum, g_blocksum);
    int*   cursor;   cudaGetSymbolAddress((void**)&cursor,   g_cursor);
    int*   csrc;     cudaGetSymbolAddress((void**)&csrc,     g_csrc);
    float* dis;      cudaGetSymbolAddress((void**)&dis,      g_dis);
    float* h1;       cudaGetSymbolAddress((void**)&h1,       g_h1);
    float* agg1;     cudaGetSymbolAddress((void**)&agg1,     g_agg1);
    float* h2;       cudaGetSymbolAddress((void**)&h2,       g_h2);

    // --- CSR build ---
    cudaMemsetAsync(deg, 0, N_NODES * sizeof(int));
    cudaMemsetAsync(cursor, 0, N_NODES * sizeof(int));
    deg_kernel<<<(N_EDGES + 255) / 256, 256>>>(dst, deg);
    dis_kernel<<<(N_NODES + 255) / 256, 256>>>(deg, dis);
    scan_pass1<<<SCAN_BLOCKS, SCAN_TPB>>>(deg, blocksum);
    scan_pass2<<<1, 256>>>(blocksum, rowptr);
    scan_pass3<<<SCAN_BLOCKS, SCAN_TPB>>>(deg, blocksum, rowptr);
    fill_kernel<<<(N_EDGES + 255) / 256, 256>>>(src, dst, rowptr, cursor, csrc);

    // --- layer 1 ---
    gemm128_kernel<128, 8><<<(N_NODES + 127) / 128, 256>>>(x, W1, h1, N_NODES);
    gather128_kernel<true><<<(N_NODES + 7) / 8, 256>>>(rowptr, csrc, dis, h1, b1, agg1);

    // --- layer 2 ---
    gemm128_kernel<64, 4><<<(N_NODES + 127) / 128, 256>>>(agg1, W2, h2, N_NODES);
    gather64_kernel<<<(N_NODES + 7) / 8, 256>>>(rowptr, csrc, dis, h2, b2, out);
}

// round 7
// speedup vs baseline: 1.2072x; 1.2072x over previous
#include <cuda_runtime.h>
#include <cstdint>

#define N_NODES 100000
#define N_EDGES 1600000
#define IN_DIM 128
#define HID_DIM 128
#define OUT_DIM 64

#define SCAN_TPB 512
#define SCAN_BLOCKS ((N_NODES + SCAN_TPB - 1) / SCAN_TPB)   // 196

// ---------------- device scratch ------------------------------------------------
__device__ int      g_deg[N_NODES];
__device__ int      g_rowptr[N_NODES + 1];
__device__ int      g_blocksum[SCAN_BLOCKS];
__device__ int      g_cursor[N_NODES];
__device__ int      g_csrc[N_EDGES];
__device__ float    g_dis[N_NODES];
__device__ float    g_h1[(size_t)N_NODES * HID_DIM];
__device__ float    g_agg1[(size_t)N_NODES * HID_DIM];
__device__ float    g_h2[(size_t)N_NODES * OUT_DIM];
__device__ uint32_t g_w1t_hi[HID_DIM * IN_DIM];   // W1^T split: [n][k]
__device__ uint32_t g_w1t_lo[HID_DIM * IN_DIM];
__device__ uint32_t g_w2t_hi[OUT_DIM * HID_DIM];  // W2^T split: [n][k]
__device__ uint32_t g_w2t_lo[OUT_DIM * HID_DIM];

// ---------------- helpers ----------------------------------------------------------
__device__ __forceinline__ uint32_t cvt_tf32(float x) {
    uint32_t r;
    asm("cvt.rna.tf32.f32 %0, %1;" : "=r"(r) : "f"(x));
    return r;
}

__device__ __forceinline__ void mma_tf32(float* d, const uint32_t* a, const uint32_t* b) {
    asm volatile(
        "mma.sync.aligned.m16n8k8.row.col.f32.tf32.tf32.f32 "
        "{%0,%1,%2,%3}, {%4,%5,%6,%7}, {%8,%9}, {%0,%1,%2,%3};"
        : "+f"(d[0]), "+f"(d[1]), "+f"(d[2]), "+f"(d[3])
        : "r"(a[0]), "r"(a[1]), "r"(a[2]), "r"(a[3]), "r"(b[0]), "r"(b[1]));
}

// ---------------- degree / norm ----------------------------------------------------
__global__ void deg_kernel(const int* __restrict__ dst, int* __restrict__ deg) {
    int i = blockIdx.x * blockDim.x + threadIdx.x;
    if (i < N_EDGES) atomicAdd(&deg[dst[i]], 1);
}
__global__ void dis_kernel(const int* __restrict__ deg, float* __restrict__ dis) {
    int i = blockIdx.x * blockDim.x + threadIdx.x;
    if (i < N_NODES) {
        float d = (float)deg[i];
        dis[i] = (d > 0.0f) ? rsqrtf(d) : 0.0f;
    }
}

// ---------------- 3-pass exclusive scan -> rowptr ----------------------------------
__global__ void scan_pass1(const int* __restrict__ deg, int* __restrict__ blocksum) {
    __shared__ int warpsum[SCAN_TPB / 32];
    int idx = blockIdx.x * SCAN_TPB + threadIdx.x;
    int v = (idx < N_NODES) ? deg[idx] : 0;
    for (int o = 16; o > 0; o >>= 1) v += __shfl_down_sync(0xffffffff, v, o);
    if ((threadIdx.x & 31) == 0) warpsum[threadIdx.x >> 5] = v;
    __syncthreads();
    if (threadIdx.x < SCAN_TPB / 32) {
        int s = warpsum[threadIdx.x];
        for (int o = 8; o > 0; o >>= 1) s += __shfl_down_sync(0xffff, s, o);
        if (threadIdx.x == 0) blocksum[blockIdx.x] = s;
    }
}
__global__ void scan_pass2(int* __restrict__ blocksum, int* __restrict__ rowptr) {
    __shared__ int ws[8];
    int lane = threadIdx.x & 31;
    int wid  = threadIdx.x >> 5;
    int v = (threadIdx.x < SCAN_BLOCKS) ? blocksum[threadIdx.x] : 0;
    int sc = v;
    for (int o = 1; o < 32; o <<= 1) {
        int t = __shfl_up_sync(0xffffffff, sc, o);
        if (lane >= o) sc += t;
    }
    if (lane == 31) ws[wid] = sc;
    __syncthreads();
    if (wid == 0 && lane < 8) {
        int s = ws[lane], ss = s;
        for (int o = 1; o < 8; o <<= 1) {
            int t = __shfl_up_sync(0xff, ss, o);
            if (lane >= o) ss += t;
        }
        ws[lane] = ss - s;
    }
    __syncthreads();
    if (threadIdx.x < SCAN_BLOCKS) blocksum[threadIdx.x] = ws[wid] + sc - v;
    if (threadIdx.x == 0) rowptr[N_NODES] = N_EDGES;
}
__global__ void scan_pass3(const int* __restrict__ deg, const int* __restrict__ blocksum,
                           int* __restrict__ rowptr) {
    __shared__ int warpsum[SCAN_TPB / 32];
    int idx = blockIdx.x * SCAN_TPB + threadIdx.x;
    int lane = threadIdx.x & 31;
    int wid  = threadIdx.x >> 5;
    int v = (idx < N_NODES) ? deg[idx] : 0;
    int sc = v;
    for (int o = 1; o < 32; o <<= 1) {
        int t = __shfl_up_sync(0xffffffff, sc, o);
        if (lane >= o) sc += t;
    }
    if (lane == 31) warpsum[wid] = sc;
    __syncthreads();
    if (wid == 0 && lane < SCAN_TPB / 32) {
        int s = warpsum[lane];
        int ss = s;
        for (int o = 1; o < SCAN_TPB / 32; o <<= 1) {
            int t = __shfl_up_sync(0xffff, ss, o);
            if (lane >= o) ss += t;
        }
        warpsum[lane] = ss - s;
    }
    __syncthreads();
    if (idx < N_NODES)
        rowptr[idx] = blocksum[blockIdx.x] + warpsum[wid] + (sc - v);
}

// ---------------- CSR fill ----------------------------------------------------------
__global__ void fill_kernel(const int* __restrict__ src, const int* __restrict__ dst,
                            const int* __restrict__ rowptr, int* __restrict__ cursor,
                            int* __restrict__ csrc) {
    int e = blockIdx.x * blockDim.x + threadIdx.x;
    if (e < N_EDGES) {
        int d = dst[e];
        int pos = rowptr[d] + atomicAdd(&cursor[d], 1);
        csrc[pos] = src[e];
    }
}

// ---------------- W transpose + tf32 split ------------------------------------------
// W: [K=128, N] row-major -> WT_hi/lo: [N][K=128] tf32 bit patterns
template<int N>
__global__ void splitW_kernel(const float* __restrict__ W,
                              uint32_t* __restrict__ WT_hi, uint32_t* __restrict__ WT_lo) {
    int idx = blockIdx.x * blockDim.x + threadIdx.x;
    if (idx < 128 * N) {
        int k = idx / N, n = idx % N;
        float w = W[idx];
        uint32_t hi = cvt_tf32(w);
        float lo = w - __uint_as_float(hi);
        WT_hi[n * 128 + k] = hi;
        WT_lo[n * 128 + k] = cvt_tf32(lo);
    }
}

// ---------------- tf32 mma.sync GEMM: C[M,N] = A[M,128] @ W[128,N] -------------------
// 256 threads = 8 warps. Warp w owns rows [w*16, w*16+16). Tile K in 2 chunks of 64.
// 3-term split: Ah*Bh + Ah*Bl + Al*Bh (fp32 accumulate).
template<int N>
__global__ void __launch_bounds__(256) gemm_mma_kernel(const float* __restrict__ A,
                                                       const uint32_t* __restrict__ BTh,
                                                       const uint32_t* __restrict__ BTl,
                                                       float* __restrict__ C, int M) {
    constexpr int BK  = 64;
    constexpr int STR = BK + 4;     // padded row stride (floats) — conflict-free frags
    constexpr int NT  = N / 8;      // n-tiles per warp

    extern __shared__ char smem[];
    float*    As  = (float*)smem;                               // [128][STR]
    uint32_t* Bhs = (uint32_t*)(smem + 128 * STR * 4);          // [N][STR]
    uint32_t* Bls = Bhs + N * STR;                              // [N][STR]

    const int tid  = threadIdx.x;
    const int w    = tid >> 5;
    const int lane = tid & 31;
    const int g    = lane >> 2;     // groupID (0..7)
    const int t    = lane & 3;      // threadID in group
    const int m0   = blockIdx.x * 128;
    const int r0   = w * 16;        // warp's row offset within tile

    float acc[NT][4];
#pragma unroll
    for (int nt = 0; nt < NT; nt++)
#pragma unroll
        for (int j = 0; j < 4; j++) acc[nt][j] = 0.0f;

#pragma unroll 1
    for (int chunk = 0; chunk < 2; chunk++) {
        const int kt = chunk * BK;
        // ---- stage A chunk: 128 rows x 64 cols, coalesced float4
#pragma unroll
        for (int i = 0; i < 8; i++) {
            int idx = tid + i * 256;        // 0..2047
            int r   = idx >> 4;             // 0..127
            int c   = idx & 15;             // float4 index (0..15)
            int gm  = m0 + r;
            float4 v = make_float4(0.f, 0.f, 0.f, 0.f);
            if (gm < M) v = *(const float4*)(A + (size_t)gm * 128 + kt + c * 4);
            *(float4*)(As + r * STR + c * 4) = v;
        }
        // ---- stage B chunk(s): N rows x 64 cols each for hi and lo
#pragma unroll
        for (int i = 0; i < N / 16; i++) {
            int idx = tid + i * 256;        // 0..N*16-1
            int r   = idx >> 4;
            int c   = idx & 15;
            *(uint4*)(Bhs + r * STR + c * 4) = *(const uint4*)(BTh + (size_t)r * 128 + kt + c * 4);
            *(uint4*)(Bls + r * STR + c * 4) = *(const uint4*)(BTl + (size_t)r * 128 + kt + c * 4);
        }
        __syncthreads();

        // ---- compute: 8 k-steps of k8
        for (int ks = 0; ks < 8; ks++) {
            const int kc = ks * 8;
            float a0 = As[(r0 + g)     * STR + kc + t];
            float a1 = As[(r0 + g + 8) * STR + kc + t];
            float a2 = As[(r0 + g)     * STR + kc + t + 4];
            float a3 = As[(r0 + g + 8) * STR + kc + t + 4];
            uint32_t ah[4], al[4];
            ah[0] = cvt_tf32(a0); al[0] = cvt_tf32(a0 - __uint_as_float(ah[0]));
            ah[1] = cvt_tf32(a1); al[1] = cvt_tf32(a1 - __uint_as_float(ah[1]));
            ah[2] = cvt_tf32(a2); al[2] = cvt_tf32(a2 - __uint_as_float(ah[2]));
            ah[3] = cvt_tf32(a3); al[3] = cvt_tf32(a3 - __uint_as_float(ah[3]));
#pragma unroll
            for (int nt = 0; nt < NT; nt++) {
                const int nrow = nt * 8 + g;
                uint32_t bh[2], bl[2];
                bh[0] = Bhs[nrow * STR + kc + t];
                bh[1] = Bhs[nrow * STR + kc + t + 4];
                bl[0] = Bls[nrow * STR + kc + t];
                bl[1] = Bls[nrow * STR + kc + t + 4];
                mma_tf32(acc[nt], ah, bh);
                mma_tf32(acc[nt], ah, bl);
                mma_tf32(acc[nt], al, bh);
            }
        }
        __syncthreads();
    }

    // ---- epilogue: c0,c1 -> (row, 2t), (row, 2t+1); c2,c3 -> row+8
    const int gr0 = m0 + r0 + g;
#pragma unroll
    for (int nt = 0; nt < NT; nt++) {
        int cc = nt * 8 + 2 * t;
        if (gr0 < M)
            *(float2*)(C + (size_t)gr0 * N + cc) = make_float2(acc[nt][0], acc[nt][1]);
        if (gr0 + 8 < M)
            *(float2*)(C + (size_t)(gr0 + 8) * N + cc) = make_float2(acc[nt][2], acc[nt][3]);
    }
}

// ---------------- CSR gather: one warp per node --------------------------------------
template<bool RELU>
__global__ void gather128_kernel(const int* __restrict__ rowptr,
                                 const int* __restrict__ csrc,
                                 const float* __restrict__ dis,
                                 const float* __restrict__ h,
                                 const float* __restrict__ bias,
                                 float* __restrict__ out) {
    const int lane = threadIdx.x & 31;
    const int node = blockIdx.x * (blockDim.x >> 5) + (threadIdx.x >> 5);
    if (node >= N_NODES) return;

    const int start = rowptr[node];
    const int end   = rowptr[node + 1];
    float4 acc = make_float4(0.f, 0.f, 0.f, 0.f);

    int j = start;
    for (; j + 2 <= end; j += 2) {
        int s0 = csrc[j], s1 = csrc[j + 1];
        float w0 = dis[s0], w1 = dis[s1];
        float4 v0 = ((const float4*)(h + (size_t)s0 * 128))[lane];
        float4 v1 = ((const float4*)(h + (size_t)s1 * 128))[lane];
        acc.x += w0 * v0.x + w1 * v1.x;
        acc.y += w0 * v0.y + w1 * v1.y;
        acc.z += w0 * v0.z + w1 * v1.z;
        acc.w += w0 * v0.w + w1 * v1.w;
    }
    if (j < end) {
        int s0 = csrc[j];
        float w0 = dis[s0];
        float4 v0 = ((const float4*)(h + (size_t)s0 * 128))[lane];
        acc.x += w0 * v0.x; acc.y += w0 * v0.y; acc.z += w0 * v0.z; acc.w += w0 * v0.w;
    }

    float dn = dis[node];
    float4 bv = ((const float4*)bias)[lane];
    float4 r;
    r.x = dn * acc.x + bv.x;
    r.y = dn * acc.y + bv.y;
    r.z = dn * acc.z + bv.z;
    r.w = dn * acc.w + bv.w;
    if (RELU) {
        r.x = fmaxf(r.x, 0.f); r.y = fmaxf(r.y, 0.f);
        r.z = fmaxf(r.z, 0.f); r.w = fmaxf(r.w, 0.f);
    }
    ((float4*)(out + (size_t)node * 128))[lane] = r;
}

__global__ void gather64_kernel(const int* __restrict__ rowptr,
                                const int* __restrict__ csrc,
                                const float* __restrict__ dis,
                                const float* __restrict__ h,
                                const float* __restrict__ bias,
                                float* __restrict__ out) {
    const int lane = threadIdx.x & 31;
    const int node = blockIdx.x * (blockDim.x >> 5) + (threadIdx.x >> 5);
    if (node >= N_NODES) return;

    const int start = rowptr[node];
    const int end   = rowptr[node + 1];
    float2 acc = make_float2(0.f, 0.f);

    int j = start;
    for (; j + 2 <= end; j += 2) {
        int s0 = csrc[j], s1 = csrc[j + 1];
        float w0 = dis[s0], w1 = dis[s1];
        float2 v0 = ((const float2*)(h + (size_t)s0 * 64))[lane];
        float2 v1 = ((const float2*)(h + (size_t)s1 * 64))[lane];
        acc.x += w0 * v0.x + w1 * v1.x;
        acc.y += w0 * v0.y + w1 * v1.y;
    }
    if (j < end) {
        int s0 = csrc[j];
        float w0 = dis[s0];
        float2 v0 = ((const float2*)(h + (size_t)s0 * 64))[lane];
        acc.x += w0 * v0.x; acc.y += w0 * v0.y;
    }

    float dn = dis[node];
    float2 bv = ((const float2*)bias)[lane];
    float2 r;
    r.x = dn * acc.x + bv.x;
    r.y = dn * acc.y + bv.y;
    ((float2*)(out + (size_t)node * 64))[lane] = r;
}

// ---------------- launch ----------------------------------------------------------
extern "C" void kernel_launch(void* const* d_in, const int* in_sizes, int n_in,
                              void* d_out, int out_size) {
    const float* x   = (const float*)d_in[0];
    const int*   ei  = (const int*)d_in[1];   // [2, E] int32
    const float* W1  = (const float*)d_in[2];
    const float* b1  = (const float*)d_in[3];
    const float* W2  = (const float*)d_in[4];
    const float* b2  = (const float*)d_in[5];
    float*       out = (float*)d_out;

    const int* src = ei;
    const int* dst = ei + N_EDGES;

    int*      deg;      cudaGetSymbolAddress((void**)&deg,      g_deg);
    int*      rowptr;   cudaGetSymbolAddress((void**)&rowptr,   g_rowptr);
    int*      blocksum; cudaGetSymbolAddress((void**)&blocksum, g_blocksum);
    int*      cursor;   cudaGetSymbolAddress((void**)&cursor,   g_cursor);
    int*      csrc;     cudaGetSymbolAddress((void**)&csrc,     g_csrc);
    float*    dis;      cudaGetSymbolAddress((void**)&dis,      g_dis);
    float*    h1;       cudaGetSymbolAddress((void**)&h1,       g_h1);
    float*    agg1;     cudaGetSymbolAddress((void**)&agg1,     g_agg1);
    float*    h2;       cudaGetSymbolAddress((void**)&h2,       g_h2);
    uint32_t* w1h;      cudaGetSymbolAddress((void**)&w1h,      g_w1t_hi);
    uint32_t* w1l;      cudaGetSymbolAddress((void**)&w1l,      g_w1t_lo);
    uint32_t* w2h;      cudaGetSymbolAddress((void**)&w2h,      g_w2t_hi);
    uint32_t* w2l;      cudaGetSymbolAddress((void**)&w2l,      g_w2t_lo);

    // dynamic smem: As[128][68] + Bh[N][68] + Bl[N][68], 4B each
    constexpr int SMEM_G1 = (128 * 68 + 2 * 128 * 68) * 4;   // 104448
    constexpr int SMEM_G2 = (128 * 68 + 2 * 64 * 68) * 4;    //  69632
    cudaFuncSetAttribute(gemm_mma_kernel<128>, cudaFuncAttributeMaxDynamicSharedMemorySize, SMEM_G1);
    cudaFuncSetAttribute(gemm_mma_kernel<64>,  cudaFuncAttributeMaxDynamicSharedMemorySize, SMEM_G2);

    // --- CSR build ---
    cudaMemsetAsync(deg, 0, N_NODES * sizeof(int));
    cudaMemsetAsync(cursor, 0, N_NODES * sizeof(int));
    deg_kernel<<<(N_EDGES + 255) / 256, 256>>>(dst, deg);
    dis_kernel<<<(N_NODES + 255) / 256, 256>>>(deg, dis);
    scan_pass1<<<SCAN_BLOCKS, SCAN_TPB>>>(deg, blocksum);
    scan_pass2<<<1, 256>>>(blocksum, rowptr);
    scan_pass3<<<SCAN_BLOCKS, SCAN_TPB>>>(deg, blocksum, rowptr);
    fill_kernel<<<(N_EDGES + 255) / 256, 256>>>(src, dst, rowptr, cursor, csrc);

    // --- weight prep: transpose + tf32 split ---
    splitW_kernel<128><<<(128 * 128 + 255) / 256, 256>>>(W1, w1h, w1l);
    splitW_kernel<64><<<(128 * 64 + 255) / 256, 256>>>(W2, w2h, w2l);

    const int gemm_grid = (N_NODES + 127) / 128;  // 782

    // --- layer 1 ---
    gemm_mma_kernel<128><<<gemm_grid, 256, SMEM_G1>>>(x, w1h, w1l, h1, N_NODES);
    gather128_kernel<true><<<(N_NODES + 7) / 8, 256>>>(rowptr, csrc, dis, h1, b1, agg1);

    // --- layer 2 ---
    gemm_mma_kernel<64><<<gemm_grid, 256, SMEM_G2>>>(agg1, w2h, w2l, h2, N_NODES);
    gather64_kernel<<<(N_NODES + 7) / 8, 256>>>(rowptr, csrc, dis, h2, b2, out);
}